// round 2
// baseline (speedup 1.0000x reference)
#include <cuda_runtime.h>
#include <math.h>

// Problem constants (fixed by the dataset)
#define BSZ   2
#define SEQL  2048
#define DM    1024
#define DI    2048      // d_inner
#define DS    16        // d_state
#define RNK   64        // dt_rank
#define XD    96        // dt_rank + 2*d_state
#define NCH   16        // number of scan chunks
#define CT    128       // chunk length (NCH*CT == SEQL)
#define ML    (BSZ*SEQL)  // 4096 rows

// ---------------- scratch (static __device__, no runtime alloc) ----------------
__device__ float g_xz    [ML * 2 * DI];       // in_proj output (x | z)
__device__ float g_xconv [ML * DI];           // conv+silu output (u)
__device__ float g_xdbl  [ML * XD];           // x_proj output (dt | B | C)
__device__ float g_delta [ML * DI];           // softplus(dt@dtW.T + b)
__device__ float g_S     [ML * DI];           // within-chunk inclusive cumsum of delta
__device__ float g_ylocal[ML * DI];           // chunk-local scan output
__device__ float g_hend  [BSZ * NCH * DS * DI];
__device__ float g_hin   [BSZ * NCH * DS * DI];
__device__ float g_yfinal[ML * DI];           // gated output, input to out_proj
__device__ float g_Aneg  [DI * DS];           // -exp(A_log)

__device__ __forceinline__ float4 ld4(const float* p) {
    return *reinterpret_cast<const float4*>(p);
}
__device__ __forceinline__ float siluf(float x) {
    return x / (1.0f + __expf(-x));
}

// ---------------- generic tiled SGEMM: C[M,N] = A[M,K] * B[N,K]^T ---------------
// epi: 0 = none, 1 = softplus(v + bias[n])
#define BM 128
#define BN 128
#define BKK 16

__global__ __launch_bounds__(256) void sgemm_tn(
    const float* __restrict__ A, int lda,
    const float* __restrict__ B, int ldb,
    float* __restrict__ C, int ldc,
    int M, int N, int K,
    const float* __restrict__ bias, int epi)
{
    __shared__ __align__(16) float As[BKK][BM + 4];
    __shared__ __align__(16) float Bs[BKK][BN + 4];

    const int tid = threadIdx.x;
    const int tx = tid & 15;       // 0..15 -> N
    const int ty = tid >> 4;       // 0..15 -> M
    const int row0 = blockIdx.y * BM;
    const int col0 = blockIdx.x * BN;

    const int lm = tid >> 1;           // 0..127 tile row
    const int lk = (tid & 1) * 8;      // 0 or 8

    float acc[8][8];
#pragma unroll
    for (int i = 0; i < 8; i++)
#pragma unroll
        for (int j = 0; j < 8; j++) acc[i][j] = 0.0f;

    for (int kk = 0; kk < K; kk += BKK) {
        // load A tile (rows of C)
        {
            int gr = row0 + lm;
            float4 v0 = make_float4(0.f,0.f,0.f,0.f), v1 = v0;
            if (gr < M) {
                const float* p = A + (size_t)gr * lda + kk + lk;
                v0 = ld4(p); v1 = ld4(p + 4);
            }
            As[lk+0][lm] = v0.x; As[lk+1][lm] = v0.y;
            As[lk+2][lm] = v0.z; As[lk+3][lm] = v0.w;
            As[lk+4][lm] = v1.x; As[lk+5][lm] = v1.y;
            As[lk+6][lm] = v1.z; As[lk+7][lm] = v1.w;
        }
        // load B tile (cols of C)
        {
            int gn = col0 + lm;
            float4 v0 = make_float4(0.f,0.f,0.f,0.f), v1 = v0;
            if (gn < N) {
                const float* p = B + (size_t)gn * ldb + kk + lk;
                v0 = ld4(p); v1 = ld4(p + 4);
            }
            Bs[lk+0][lm] = v0.x; Bs[lk+1][lm] = v0.y;
            Bs[lk+2][lm] = v0.z; Bs[lk+3][lm] = v0.w;
            Bs[lk+4][lm] = v1.x; Bs[lk+5][lm] = v1.y;
            Bs[lk+6][lm] = v1.z; Bs[lk+7][lm] = v1.w;
        }
        __syncthreads();

#pragma unroll
        for (int k = 0; k < BKK; k++) {
            float4 a0 = *reinterpret_cast<const float4*>(&As[k][ty*8]);
            float4 a1 = *reinterpret_cast<const float4*>(&As[k][ty*8+4]);
            float4 b0 = *reinterpret_cast<const float4*>(&Bs[k][tx*8]);
            float4 b1 = *reinterpret_cast<const float4*>(&Bs[k][tx*8+4]);
            float av[8] = {a0.x,a0.y,a0.z,a0.w,a1.x,a1.y,a1.z,a1.w};
            float bv[8] = {b0.x,b0.y,b0.z,b0.w,b1.x,b1.y,b1.z,b1.w};
#pragma unroll
            for (int i = 0; i < 8; i++)
#pragma unroll
                for (int j = 0; j < 8; j++)
                    acc[i][j] = fmaf(av[i], bv[j], acc[i][j]);
        }
        __syncthreads();
    }

#pragma unroll
    for (int i = 0; i < 8; i++) {
        int r = row0 + ty*8 + i;
        if (r >= M) continue;
#pragma unroll
        for (int j = 0; j < 8; j++) {
            int c = col0 + tx*8 + j;
            if (c >= N) continue;
            float v = acc[i][j];
            if (epi == 1) {
                v += bias[c];
                v = (v > 20.0f) ? v : log1pf(__expf(v));   // softplus
            }
            C[(size_t)r * ldc + c] = v;
        }
    }
}

// ---------------- depthwise causal conv (K=4) + bias + SiLU ---------------------
__global__ __launch_bounds__(256) void conv_silu_kernel(
    const float* __restrict__ conv_w,   // [DI,1,4]
    const float* __restrict__ conv_b)   // [DI]
{
    int d = blockIdx.x * 256 + threadIdx.x;   // 0..DI-1
    int l = blockIdx.y;
    int b = blockIdx.z;
    float4 w = ld4(conv_w + d * 4);
    const float wv[4] = {w.x, w.y, w.z, w.w};
    float acc = conv_b[d];
    int base = b * SEQL;
#pragma unroll
    for (int k = 0; k < 4; k++) {
        int li = l - 3 + k;
        if (li >= 0)
            acc = fmaf(g_xz[(size_t)(base + li) * (2*DI) + d], wv[k], acc);
    }
    g_xconv[(size_t)(base + l) * DI + d] = siluf(acc);
}

// ---------------- x_proj GEMM (N=96, K=2048): dedicated small-N kernel ----------
__global__ __launch_bounds__(256) void gemm_xdbl_kernel(
    const float* __restrict__ W)   // x_proj_w [96, 2048]
{
    __shared__ float As[32][33];
    __shared__ float Ws[96][33];
    int tid = threadIdx.x;
    int row0 = blockIdx.x * 32;
    int r = tid & 31;
    int g = tid >> 5;          // 0..7, cols g*12..g*12+11
    float acc[12];
#pragma unroll
    for (int j = 0; j < 12; j++) acc[j] = 0.0f;

    for (int kk = 0; kk < DI; kk += 32) {
#pragma unroll
        for (int i = 0; i < 4; i++) {
            int e = tid + i * 256;
            int m = e >> 5, k = e & 31;
            As[m][k] = g_xconv[(size_t)(row0 + m) * DI + kk + k];
        }
#pragma unroll
        for (int i = 0; i < 12; i++) {
            int e = tid + i * 256;
            int n = e >> 5, k = e & 31;
            Ws[n][k] = W[(size_t)n * DI + kk + k];
        }
        __syncthreads();
#pragma unroll
        for (int k = 0; k < 32; k++) {
            float a = As[r][k];
#pragma unroll
            for (int j = 0; j < 12; j++)
                acc[j] = fmaf(a, Ws[g*12 + j][k], acc[j]);
        }
        __syncthreads();
    }
#pragma unroll
    for (int j = 0; j < 12; j++)
        g_xdbl[(size_t)(row0 + r) * XD + g*12 + j] = acc[j];
}

// ---------------- prep: Aneg = -exp(A_log) --------------------------------------
__global__ void prep_A_kernel(const float* __restrict__ A_log) {
    int i = blockIdx.x * 256 + threadIdx.x;
    if (i < DI * DS) g_Aneg[i] = -__expf(A_log[i]);
}

// ---------------- scan phase A: chunk-local scan (h0 = 0) -----------------------
// thread = (b, chunk, d). Writes y_local, S (inclusive cum-delta), h_end.
__global__ __launch_bounds__(256) void scanA_kernel()
{
    int bc = blockIdx.x;                     // 0..255
    int d     = (bc & 7) * 256 + threadIdx.x;
    int chunk = (bc >> 3) & 15;
    int b     = bc >> 7;

    float a[DS], h[DS];
#pragma unroll
    for (int n = 0; n < DS; n++) { a[n] = g_Aneg[d * DS + n]; h[n] = 0.0f; }
    float S = 0.0f;
    int l0 = chunk * CT;

    for (int t = 0; t < CT; t++) {
        size_t base = (size_t)(b * SEQL + l0 + t);
        float dlt = g_delta[base * DI + d];
        float u   = g_xconv[base * DI + d];
        S += dlt;
        g_S[base * DI + d] = S;
        float du = dlt * u;
        const float* bc_ptr = g_xdbl + base * XD + RNK;
        float4 B0 = ld4(bc_ptr), B1 = ld4(bc_ptr + 4);
        float4 B2 = ld4(bc_ptr + 8), B3 = ld4(bc_ptr + 12);
        float4 C0 = ld4(bc_ptr + 16), C1 = ld4(bc_ptr + 20);
        float4 C2 = ld4(bc_ptr + 24), C3 = ld4(bc_ptr + 28);
        float Bv[DS] = {B0.x,B0.y,B0.z,B0.w,B1.x,B1.y,B1.z,B1.w,
                        B2.x,B2.y,B2.z,B2.w,B3.x,B3.y,B3.z,B3.w};
        float Cv[DS] = {C0.x,C0.y,C0.z,C0.w,C1.x,C1.y,C1.z,C1.w,
                        C2.x,C2.y,C2.z,C2.w,C3.x,C3.y,C3.z,C3.w};
        float y = 0.0f;
#pragma unroll
        for (int n = 0; n < DS; n++) {
            float dA = __expf(a[n] * dlt);
            h[n] = fmaf(h[n], dA, du * Bv[n]);
            y = fmaf(h[n], Cv[n], y);
        }
        g_ylocal[base * DI + d] = y;
    }
#pragma unroll
    for (int n = 0; n < DS; n++)
        g_hend[((size_t)(b * NCH + chunk) * DS + n) * DI + d] = h[n];
}

// ---------------- scan phase B: cross-chunk prefix (16 steps) -------------------
// thread = (b, n, d). h_in[c] = exclusive prefix of chunk contributions.
__global__ __launch_bounds__(256) void scanB_kernel()
{
    int bc = blockIdx.x;                     // 0..255
    int d = (bc & 7) * 256 + threadIdx.x;
    int n = (bc >> 3) & 15;
    int b = bc >> 7;
    float an = g_Aneg[d * DS + n];
    float hin = 0.0f;
    for (int c = 0; c < NCH; c++) {
        size_t idx = ((size_t)(b * NCH + c) * DS + n) * DI + d;
        g_hin[idx] = hin;
        float Sc = g_S[(size_t)(b * SEQL + c * CT + CT - 1) * DI + d];
        hin = fmaf(hin, __expf(an * Sc), g_hend[idx]);
    }
}

// ---------------- scan phase C: correction + D*x + silu(z) gate -----------------
__global__ __launch_bounds__(256) void scanC_kernel(const float* __restrict__ Dp)
{
    int d = blockIdx.x * 256 + threadIdx.x;
    int l = blockIdx.y;
    int b = blockIdx.z;
    size_t base = (size_t)(b * SEQL + l);
    int chunk = l >> 7;

    float S = g_S[base * DI + d];
    float y = g_ylocal[base * DI + d];
    const float* cp = g_xdbl + base * XD + RNK + DS;
    float4 C0 = ld4(cp), C1 = ld4(cp + 4), C2 = ld4(cp + 8), C3 = ld4(cp + 12);
    float Cv[DS] = {C0.x,C0.y,C0.z,C0.w,C1.x,C1.y,C1.z,C1.w,
                    C2.x,C2.y,C2.z,C2.w,C3.x,C3.y,C3.z,C3.w};
#pragma unroll
    for (int n = 0; n < DS; n++) {
        float an = g_Aneg[d * DS + n];
        float hin = g_hin[((size_t)(b * NCH + chunk) * DS + n) * DI + d];
        y = fmaf(Cv[n] * __expf(an * S), hin, y);
    }
    float x = g_xconv[base * DI + d];
    float z = g_xz[base * (2*DI) + DI + d];
    y = fmaf(Dp[d], x, y);
    g_yfinal[base * DI + d] = y * siluf(z);
}

// ---------------- launch --------------------------------------------------------
extern "C" void kernel_launch(void* const* d_in, const int* in_sizes, int n_in,
                              void* d_out, int out_size)
{
    const float* hidden    = (const float*)d_in[0];   // [2,2048,1024]
    const float* in_proj_w = (const float*)d_in[1];   // [4096,1024]
    const float* conv_w    = (const float*)d_in[2];   // [2048,1,4]
    const float* conv_b    = (const float*)d_in[3];   // [2048]
    const float* x_proj_w  = (const float*)d_in[4];   // [96,2048]
    const float* dt_proj_w = (const float*)d_in[5];   // [2048,64]
    const float* dt_proj_b = (const float*)d_in[6];   // [2048]
    const float* A_log     = (const float*)d_in[7];   // [2048,16]
    const float* Dp        = (const float*)d_in[8];   // [2048]
    const float* out_proj_w= (const float*)d_in[9];   // [1024,2048]
    float* out = (float*)d_out;                       // [2,2048,1024]

    float* xz     = nullptr; cudaGetSymbolAddress((void**)&xz,     g_xz);
    float* xdbl   = nullptr; cudaGetSymbolAddress((void**)&xdbl,   g_xdbl);
    float* delta  = nullptr; cudaGetSymbolAddress((void**)&delta,  g_delta);
    float* yfinal = nullptr; cudaGetSymbolAddress((void**)&yfinal, g_yfinal);

    // 1) xz = hidden @ in_proj_w^T            [4096 x 4096], K=1024
    sgemm_tn<<<dim3(32, 32), 256>>>(hidden, DM, in_proj_w, DM,
                                    xz, 2*DI, ML, 2*DI, DM, nullptr, 0);
    // 2) depthwise conv + silu
    conv_silu_kernel<<<dim3(DI/256, SEQL, BSZ), 256>>>(conv_w, conv_b);
    // 3) Aneg = -exp(A_log)
    prep_A_kernel<<<(DI*DS + 255)/256, 256>>>(A_log);
    // 4) x_dbl = xconv @ x_proj_w^T           [4096 x 96], K=2048
    gemm_xdbl_kernel<<<ML/32, 256>>>(x_proj_w);
    // 5) delta = softplus(x_dbl[:, :64] @ dt_proj_w^T + b)   [4096 x 2048], K=64
    sgemm_tn<<<dim3(DI/BN, ML/BM), 256>>>(xdbl, XD, dt_proj_w, RNK,
                                          delta, DI, ML, DI, RNK, dt_proj_b, 1);
    // 6) chunked selective scan
    scanA_kernel<<<BSZ*NCH*(DI/256), 256>>>();
    scanB_kernel<<<BSZ*DS*(DI/256), 256>>>();
    scanC_kernel<<<dim3(DI/256, SEQL, BSZ), 256>>>(Dp);
    // 7) out = yfinal @ out_proj_w^T          [4096 x 1024], K=2048
    sgemm_tn<<<dim3(DM/BN, ML/BM), 256>>>(yfinal, DI, out_proj_w, DI,
                                          out, DM, ML, DM, DI, nullptr, 0);
}

// round 6
// speedup vs baseline: 2.5905x; 2.5905x over previous
#include <cuda_runtime.h>
#include <cuda_bf16.h>
#include <stdint.h>
#include <math.h>

// Problem constants (fixed by the dataset)
#define BSZ   2
#define SEQL  2048
#define DM    1024
#define DI    2048      // d_inner
#define DS    16        // d_state
#define RNK   64        // dt_rank
#define XD    96        // dt_rank + 2*d_state
#define NCH   16        // number of scan chunks
#define CT    128       // chunk length (NCH*CT == SEQL)
#define ML    (BSZ*SEQL)  // 4096 rows

// ---------------- scratch (static __device__, no runtime alloc) ----------------
__device__ float g_xz    [ML * 2 * DI];       // in_proj output (x | z)
__device__ float g_xconv [ML * DI];           // conv+silu output (u)
__device__ float g_xdbl  [ML * XD];           // x_proj output (dt | B | C)
__device__ float g_delta [ML * DI];           // softplus(dt@dtW.T + b)
__device__ float g_S     [ML * DI];           // within-chunk inclusive cumsum of delta
__device__ float g_ylocal[ML * DI];           // chunk-local scan output
__device__ float g_hend  [BSZ * NCH * DS * DI];
__device__ float g_hin   [BSZ * NCH * DS * DI];
__device__ float g_yfinal[ML * DI];           // gated output, input to out_proj
__device__ float g_Aneg  [DI * DS];           // -exp(A_log)

// split-bf16 operand buffers (ushort bit patterns)
__device__ unsigned short g_a1[ML * 3 * DM];        // hidden split   [4096 x 3072]
__device__ unsigned short g_b1[(2*DI) * 3 * DM];    // in_proj_w split[4096 x 3072]
__device__ unsigned short g_a2[ML * 3 * DI];        // yfinal split   [4096 x 6144]
__device__ unsigned short g_b2[DM * 3 * DI];        // out_proj_w split[1024 x 6144]

__device__ __forceinline__ float4 ld4(const float* p) {
    return *reinterpret_cast<const float4*>(p);
}
__device__ __forceinline__ float siluf(float x) {
    return x / (1.0f + __expf(-x));
}

// ---------------- split-bf16 conversion ----------------------------------------
// mode 0 (A operand): Y[M,3K] = [hi | hi | lo]
// mode 1 (B operand): Y[M,3K] = [hi | lo | hi]
// Together: A'.B' = hi.hi + hi.lo + lo.hi  (lo.lo dropped, ~2^-18 relative)
__global__ __launch_bounds__(256) void split_bf16_kernel(
    const float* __restrict__ X, unsigned short* __restrict__ Y,
    int K, int total, int mode)
{
    int idx = blockIdx.x * 256 + threadIdx.x;
    if (idx >= total) return;
    int m = idx / K;
    int k = idx - m * K;
    float x = X[idx];
    __nv_bfloat16 hi = __float2bfloat16(x);
    float lof = x - __bfloat162float(hi);
    __nv_bfloat16 lo = __float2bfloat16(lof);
    unsigned short hb = __bfloat16_as_ushort(hi);
    unsigned short lb = __bfloat16_as_ushort(lo);
    size_t base = (size_t)m * 3 * K;
    Y[base + k] = hb;
    if (mode == 0) {
        Y[base + K + k]     = hb;
        Y[base + 2 * K + k] = lb;
    } else {
        Y[base + K + k]     = lb;
        Y[base + 2 * K + k] = hb;
    }
}

// ---------------- bf16 tensor-core GEMM: C[M,N] = A[M,K2] * B[N,K2]^T ----------
// 128x128x32 block tile, 128 threads, 4 warps of 64x64, cp.async double buffer.
#define TBK 32
#define SPAD 8
#define SLD  (TBK + SPAD)   // 40 elements per smem row

__device__ __forceinline__ void cpasync16(unsigned int saddr, const void* gptr) {
    asm volatile("cp.async.cg.shared.global [%0], [%1], 16;\n" :: "r"(saddr), "l"(gptr));
}

__global__ __launch_bounds__(128) void gemm_bf16_split(
    const unsigned short* __restrict__ A,   // [M][K2] bf16 bits
    const unsigned short* __restrict__ B,   // [N][K2] bf16 bits
    float* __restrict__ C, int ldc,
    int K2)
{
    __shared__ __align__(16) unsigned short sm[2][2][128][SLD];

    const int tid  = threadIdx.x;
    const int lane = tid & 31;
    const int wid  = tid >> 5;
    const int wm   = (wid >> 1) * 64;    // warp M offset
    const int wn   = (wid & 1) * 64;     // warp N offset
    const int row0 = blockIdx.y * 128;
    const int col0 = blockIdx.x * 128;

    const int T = K2 / TBK;

    float acc[4][8][4];
#pragma unroll
    for (int mi = 0; mi < 4; mi++)
#pragma unroll
        for (int ni = 0; ni < 8; ni++)
#pragma unroll
            for (int q = 0; q < 4; q++) acc[mi][ni][q] = 0.0f;

    auto issue = [&](int t, int buf) {
        int kk = t * TBK;
#pragma unroll
        for (int i = 0; i < 4; i++) {
            int e = tid + 128 * i;
            int r = e >> 2;
            int c = e & 3;
            unsigned int sa = (unsigned int)__cvta_generic_to_shared(&sm[buf][0][r][c * 8]);
            cpasync16(sa, A + (size_t)(row0 + r) * K2 + kk + c * 8);
            unsigned int sb = (unsigned int)__cvta_generic_to_shared(&sm[buf][1][r][c * 8]);
            cpasync16(sb, B + (size_t)(col0 + r) * K2 + kk + c * 8);
        }
        asm volatile("cp.async.commit_group;\n");
    };

    issue(0, 0);

    for (int t = 0; t < T; t++) {
        if (t + 1 < T) {
            issue(t + 1, (t + 1) & 1);
            asm volatile("cp.async.wait_group 1;\n");
        } else {
            asm volatile("cp.async.wait_group 0;\n");
        }
        __syncthreads();

        const unsigned short (*As)[SLD] = sm[t & 1][0];
        const unsigned short (*Bs)[SLD] = sm[t & 1][1];

#pragma unroll
        for (int ks = 0; ks < 2; ks++) {
            const int kc = ks * 16 + (lane & 3) * 2;
            unsigned int af[4][4], bf[8][2];
#pragma unroll
            for (int mi = 0; mi < 4; mi++) {
                int r = wm + mi * 16 + (lane >> 2);
                af[mi][0] = *(const unsigned int*)&As[r][kc];
                af[mi][1] = *(const unsigned int*)&As[r + 8][kc];
                af[mi][2] = *(const unsigned int*)&As[r][kc + 8];
                af[mi][3] = *(const unsigned int*)&As[r + 8][kc + 8];
            }
#pragma unroll
            for (int ni = 0; ni < 8; ni++) {
                int n = wn + ni * 8 + (lane >> 2);
                bf[ni][0] = *(const unsigned int*)&Bs[n][kc];
                bf[ni][1] = *(const unsigned int*)&Bs[n][kc + 8];
            }
#pragma unroll
            for (int mi = 0; mi < 4; mi++)
#pragma unroll
                for (int ni = 0; ni < 8; ni++) {
                    asm volatile(
                        "mma.sync.aligned.m16n8k16.row.col.f32.bf16.bf16.f32 "
                        "{%0,%1,%2,%3}, {%4,%5,%6,%7}, {%8,%9}, {%0,%1,%2,%3};"
                        : "+f"(acc[mi][ni][0]), "+f"(acc[mi][ni][1]),
                          "+f"(acc[mi][ni][2]), "+f"(acc[mi][ni][3])
                        : "r"(af[mi][0]), "r"(af[mi][1]), "r"(af[mi][2]), "r"(af[mi][3]),
                          "r"(bf[ni][0]), "r"(bf[ni][1]));
                }
        }
        __syncthreads();
    }

    // epilogue
#pragma unroll
    for (int mi = 0; mi < 4; mi++) {
        int r = row0 + wm + mi * 16 + (lane >> 2);
#pragma unroll
        for (int ni = 0; ni < 8; ni++) {
            int cn = col0 + wn + ni * 8 + (lane & 3) * 2;
            *(float2*)&C[(size_t)r * ldc + cn] =
                make_float2(acc[mi][ni][0], acc[mi][ni][1]);
            *(float2*)&C[(size_t)(r + 8) * ldc + cn] =
                make_float2(acc[mi][ni][2], acc[mi][ni][3]);
        }
    }
}

// ---------------- fp32 tiled SGEMM (kept for dt_proj, K=64) ---------------------
#define BM 128
#define BN 128
#define BKK 16

__global__ __launch_bounds__(256) void sgemm_tn(
    const float* __restrict__ A, int lda,
    const float* __restrict__ B, int ldb,
    float* __restrict__ C, int ldc,
    int M, int N, int K,
    const float* __restrict__ bias, int epi)
{
    __shared__ __align__(16) float As[BKK][BM + 4];
    __shared__ __align__(16) float Bs[BKK][BN + 4];

    const int tid = threadIdx.x;
    const int tx = tid & 15;
    const int ty = tid >> 4;
    const int row0 = blockIdx.y * BM;
    const int col0 = blockIdx.x * BN;

    const int lm = tid >> 1;
    const int lk = (tid & 1) * 8;

    float acc[8][8];
#pragma unroll
    for (int i = 0; i < 8; i++)
#pragma unroll
        for (int j = 0; j < 8; j++) acc[i][j] = 0.0f;

    for (int kk = 0; kk < K; kk += BKK) {
        {
            int gr = row0 + lm;
            float4 v0 = make_float4(0.f,0.f,0.f,0.f), v1 = v0;
            if (gr < M) {
                const float* p = A + (size_t)gr * lda + kk + lk;
                v0 = ld4(p); v1 = ld4(p + 4);
            }
            As[lk+0][lm] = v0.x; As[lk+1][lm] = v0.y;
            As[lk+2][lm] = v0.z; As[lk+3][lm] = v0.w;
            As[lk+4][lm] = v1.x; As[lk+5][lm] = v1.y;
            As[lk+6][lm] = v1.z; As[lk+7][lm] = v1.w;
        }
        {
            int gn = col0 + lm;
            float4 v0 = make_float4(0.f,0.f,0.f,0.f), v1 = v0;
            if (gn < N) {
                const float* p = B + (size_t)gn * ldb + kk + lk;
                v0 = ld4(p); v1 = ld4(p + 4);
            }
            Bs[lk+0][lm] = v0.x; Bs[lk+1][lm] = v0.y;
            Bs[lk+2][lm] = v0.z; Bs[lk+3][lm] = v0.w;
            Bs[lk+4][lm] = v1.x; Bs[lk+5][lm] = v1.y;
            Bs[lk+6][lm] = v1.z; Bs[lk+7][lm] = v1.w;
        }
        __syncthreads();

#pragma unroll
        for (int k = 0; k < BKK; k++) {
            float4 a0 = *reinterpret_cast<const float4*>(&As[k][ty*8]);
            float4 a1 = *reinterpret_cast<const float4*>(&As[k][ty*8+4]);
            float4 b0 = *reinterpret_cast<const float4*>(&Bs[k][tx*8]);
            float4 b1 = *reinterpret_cast<const float4*>(&Bs[k][tx*8+4]);
            float av[8] = {a0.x,a0.y,a0.z,a0.w,a1.x,a1.y,a1.z,a1.w};
            float bv[8] = {b0.x,b0.y,b0.z,b0.w,b1.x,b1.y,b1.z,b1.w};
#pragma unroll
            for (int i = 0; i < 8; i++)
#pragma unroll
                for (int j = 0; j < 8; j++)
                    acc[i][j] = fmaf(av[i], bv[j], acc[i][j]);
        }
        __syncthreads();
    }

#pragma unroll
    for (int i = 0; i < 8; i++) {
        int r = row0 + ty*8 + i;
        if (r >= M) continue;
#pragma unroll
        for (int j = 0; j < 8; j++) {
            int c = col0 + tx*8 + j;
            if (c >= N) continue;
            float v = acc[i][j];
            if (epi == 1) {
                v += bias[c];
                v = (v > 20.0f) ? v : log1pf(__expf(v));   // softplus
            }
            C[(size_t)r * ldc + c] = v;
        }
    }
}

// ---------------- depthwise causal conv (K=4) + bias + SiLU ---------------------
__global__ __launch_bounds__(256) void conv_silu_kernel(
    const float* __restrict__ conv_w,
    const float* __restrict__ conv_b)
{
    int d = blockIdx.x * 256 + threadIdx.x;
    int l = blockIdx.y;
    int b = blockIdx.z;
    float4 w = ld4(conv_w + d * 4);
    const float wv[4] = {w.x, w.y, w.z, w.w};
    float acc = conv_b[d];
    int base = b * SEQL;
#pragma unroll
    for (int k = 0; k < 4; k++) {
        int li = l - 3 + k;
        if (li >= 0)
            acc = fmaf(g_xz[(size_t)(base + li) * (2*DI) + d], wv[k], acc);
    }
    g_xconv[(size_t)(base + l) * DI + d] = siluf(acc);
}

// ---------------- x_proj GEMM: split-K x4 with atomic accumulation --------------
__global__ __launch_bounds__(256) void gemm_xdbl_splitk(
    const float* __restrict__ W)   // x_proj_w [96, 2048]
{
    __shared__ float As[32][33];
    __shared__ float Ws[96][33];
    int tid = threadIdx.x;
    int row0 = blockIdx.x * 32;
    int kq = blockIdx.y;           // 0..3, K chunk of 512
    int r = tid & 31;
    int g = tid >> 5;
    float acc[12];
#pragma unroll
    for (int j = 0; j < 12; j++) acc[j] = 0.0f;

    for (int kk = kq * 512; kk < (kq + 1) * 512; kk += 32) {
#pragma unroll
        for (int i = 0; i < 4; i++) {
            int e = tid + i * 256;
            int m = e >> 5, k = e & 31;
            As[m][k] = g_xconv[(size_t)(row0 + m) * DI + kk + k];
        }
#pragma unroll
        for (int i = 0; i < 12; i++) {
            int e = tid + i * 256;
            int n = e >> 5, k = e & 31;
            Ws[n][k] = W[(size_t)n * DI + kk + k];
        }
        __syncthreads();
#pragma unroll
        for (int k = 0; k < 32; k++) {
            float a = As[r][k];
#pragma unroll
            for (int j = 0; j < 12; j++)
                acc[j] = fmaf(a, Ws[g*12 + j][k], acc[j]);
        }
        __syncthreads();
    }
#pragma unroll
    for (int j = 0; j < 12; j++)
        atomicAdd(&g_xdbl[(size_t)(row0 + r) * XD + g*12 + j], acc[j]);
}

// ---------------- prep: Aneg = -exp(A_log) --------------------------------------
__global__ void prep_A_kernel(const float* __restrict__ A_log) {
    int i = blockIdx.x * 256 + threadIdx.x;
    if (i < DI * DS) g_Aneg[i] = -__expf(A_log[i]);
}

// ---------------- scan phase A: chunk-local scan (h0 = 0) -----------------------
__global__ __launch_bounds__(256) void scanA_kernel()
{
    int bc = blockIdx.x;
    int d     = (bc & 7) * 256 + threadIdx.x;
    int chunk = (bc >> 3) & 15;
    int b     = bc >> 7;

    float a[DS], h[DS];
#pragma unroll
    for (int n = 0; n < DS; n++) { a[n] = g_Aneg[d * DS + n]; h[n] = 0.0f; }
    float S = 0.0f;
    int l0 = chunk * CT;

    for (int t = 0; t < CT; t++) {
        size_t base = (size_t)(b * SEQL + l0 + t);
        float dlt = g_delta[base * DI + d];
        float u   = g_xconv[base * DI + d];
        S += dlt;
        g_S[base * DI + d] = S;
        float du = dlt * u;
        const float* bc_ptr = g_xdbl + base * XD + RNK;
        float4 B0 = ld4(bc_ptr), B1 = ld4(bc_ptr + 4);
        float4 B2 = ld4(bc_ptr + 8), B3 = ld4(bc_ptr + 12);
        float4 C0 = ld4(bc_ptr + 16), C1 = ld4(bc_ptr + 20);
        float4 C2 = ld4(bc_ptr + 24), C3 = ld4(bc_ptr + 28);
        float Bv[DS] = {B0.x,B0.y,B0.z,B0.w,B1.x,B1.y,B1.z,B1.w,
                        B2.x,B2.y,B2.z,B2.w,B3.x,B3.y,B3.z,B3.w};
        float Cv[DS] = {C0.x,C0.y,C0.z,C0.w,C1.x,C1.y,C1.z,C1.w,
                        C2.x,C2.y,C2.z,C2.w,C3.x,C3.y,C3.z,C3.w};
        float y = 0.0f;
#pragma unroll
        for (int n = 0; n < DS; n++) {
            float dA = __expf(a[n] * dlt);
            h[n] = fmaf(h[n], dA, du * Bv[n]);
            y = fmaf(h[n], Cv[n], y);
        }
        g_ylocal[base * DI + d] = y;
    }
#pragma unroll
    for (int n = 0; n < DS; n++)
        g_hend[((size_t)(b * NCH + chunk) * DS + n) * DI + d] = h[n];
}

// ---------------- scan phase B: cross-chunk prefix (16 steps) -------------------
__global__ __launch_bounds__(256) void scanB_kernel()
{
    int bc = blockIdx.x;
    int d = (bc & 7) * 256 + threadIdx.x;
    int n = (bc >> 3) & 15;
    int b = bc >> 7;
    float an = g_Aneg[d * DS + n];
    float hin = 0.0f;
    for (int c = 0; c < NCH; c++) {
        size_t idx = ((size_t)(b * NCH + c) * DS + n) * DI + d;
        g_hin[idx] = hin;
        float Sc = g_S[(size_t)(b * SEQL + c * CT + CT - 1) * DI + d];
        hin = fmaf(hin, __expf(an * Sc), g_hend[idx]);
    }
}

// ---------------- scan phase C: correction + D*x + silu(z) gate -----------------
__global__ __launch_bounds__(256) void scanC_kernel(const float* __restrict__ Dp)
{
    int d = blockIdx.x * 256 + threadIdx.x;
    int l = blockIdx.y;
    int b = blockIdx.z;
    size_t base = (size_t)(b * SEQL + l);
    int chunk = l >> 7;

    float S = g_S[base * DI + d];
    float y = g_ylocal[base * DI + d];
    const float* cp = g_xdbl + base * XD + RNK + DS;
    float4 C0 = ld4(cp), C1 = ld4(cp + 4), C2 = ld4(cp + 8), C3 = ld4(cp + 12);
    float Cv[DS] = {C0.x,C0.y,C0.z,C0.w,C1.x,C1.y,C1.z,C1.w,
                    C2.x,C2.y,C2.z,C2.w,C3.x,C3.y,C3.z,C3.w};
#pragma unroll
    for (int n = 0; n < DS; n++) {
        float an = g_Aneg[d * DS + n];
        float hin = g_hin[((size_t)(b * NCH + chunk) * DS + n) * DI + d];
        y = fmaf(Cv[n] * __expf(an * S), hin, y);
    }
    float x = g_xconv[base * DI + d];
    float z = g_xz[base * (2*DI) + DI + d];
    y = fmaf(Dp[d], x, y);
    g_yfinal[base * DI + d] = y * siluf(z);
}

// ---------------- launch --------------------------------------------------------
extern "C" void kernel_launch(void* const* d_in, const int* in_sizes, int n_in,
                              void* d_out, int out_size)
{
    const float* hidden    = (const float*)d_in[0];   // [2,2048,1024]
    const float* in_proj_w = (const float*)d_in[1];   // [4096,1024]
    const float* conv_w    = (const float*)d_in[2];   // [2048,1,4]
    const float* conv_b    = (const float*)d_in[3];   // [2048]
    const float* x_proj_w  = (const float*)d_in[4];   // [96,2048]
    const float* dt_proj_w = (const float*)d_in[5];   // [2048,64]
    const float* dt_proj_b = (const float*)d_in[6];   // [2048]
    const float* A_log     = (const float*)d_in[7];   // [2048,16]
    const float* Dp        = (const float*)d_in[8];   // [2048]
    const float* out_proj_w= (const float*)d_in[9];   // [1024,2048]
    float* out = (float*)d_out;                       // [2,2048,1024]

    float* xz     = nullptr; cudaGetSymbolAddress((void**)&xz,     g_xz);
    float* xdbl   = nullptr; cudaGetSymbolAddress((void**)&xdbl,   g_xdbl);
    float* delta  = nullptr; cudaGetSymbolAddress((void**)&delta,  g_delta);
    float* yfinal = nullptr; cudaGetSymbolAddress((void**)&yfinal, g_yfinal);
    unsigned short* a1 = nullptr; cudaGetSymbolAddress((void**)&a1, g_a1);
    unsigned short* b1 = nullptr; cudaGetSymbolAddress((void**)&b1, g_b1);
    unsigned short* a2 = nullptr; cudaGetSymbolAddress((void**)&a2, g_a2);
    unsigned short* b2 = nullptr; cudaGetSymbolAddress((void**)&b2, g_b2);

    // 0) split-bf16 conversions for GEMM1 (A: [hi|hi|lo], B: [hi|lo|hi])
    {
        int tot = ML * DM;
        split_bf16_kernel<<<(tot + 255)/256, 256>>>(hidden, a1, DM, tot, 0);
        tot = (2*DI) * DM;
        split_bf16_kernel<<<(tot + 255)/256, 256>>>(in_proj_w, b1, DM, tot, 1);
    }
    // 1) xz = hidden @ in_proj_w^T via split-bf16 tensor GEMM (K2 = 3*1024)
    gemm_bf16_split<<<dim3((2*DI)/128, ML/128), 128>>>(a1, b1, xz, 2*DI, 3*DM);
    // 2) depthwise conv + silu
    conv_silu_kernel<<<dim3(DI/256, SEQL, BSZ), 256>>>(conv_w, conv_b);
    // 3) Aneg = -exp(A_log)
    prep_A_kernel<<<(DI*DS + 255)/256, 256>>>(A_log);
    // 4) x_dbl = xconv @ x_proj_w^T  (split-K x4 + atomics)
    cudaMemsetAsync(xdbl, 0, (size_t)ML * XD * sizeof(float));
    gemm_xdbl_splitk<<<dim3(ML/32, 4), 256>>>(x_proj_w);
    // 5) delta = softplus(x_dbl[:, :64] @ dt_proj_w^T + b)
    sgemm_tn<<<dim3(DI/BN, ML/BM), 256>>>(xdbl, XD, dt_proj_w, RNK,
                                          delta, DI, ML, DI, RNK, dt_proj_b, 1);
    // 6) chunked selective scan
    scanA_kernel<<<BSZ*NCH*(DI/256), 256>>>();
    scanB_kernel<<<BSZ*DS*(DI/256), 256>>>();
    scanC_kernel<<<dim3(DI/256, SEQL, BSZ), 256>>>(Dp);
    // 7) split-bf16 conversions for GEMM_out (A: [hi|hi|lo], B: [hi|lo|hi])
    {
        int tot = ML * DI;
        split_bf16_kernel<<<(tot + 255)/256, 256>>>(yfinal, a2, DI, tot, 0);
        tot = DM * DI;
        split_bf16_kernel<<<(tot + 255)/256, 256>>>(out_proj_w, b2, DI, tot, 1);
    }
    // 8) out = yfinal @ out_proj_w^T via split-bf16 tensor GEMM (K2 = 3*2048)
    gemm_bf16_split<<<dim3(DM/128, ML/128), 128>>>(a2, b2, out, DM, 3*DI);
}